// round 13
// baseline (speedup 1.0000x reference)
#include <cuda_runtime.h>
#include <cuda_bf16.h>
#include <cstdint>

// ---------------------------------------------------------------------------
// LocalAttentionBlock on GB300 (base sm_103 target): bf16 mma.sync m16n8k16
// GEMMs (32x64 warp tiles, double-buffered cp.async) + smem-tiled NATTEN,
// norm2 fused into proj epilogue, fast MUFU-based asinh.
// B=16, H=W=64, C=256, heads=8, hd=32
// ---------------------------------------------------------------------------

#define TOKENS   65536
#define C_DIM    256
#define QKV_DIM  768
#define FF_DIM   512
#define NHEADS   8
#define HDIM     32

// Scratch (device globals — allocation-free rule)
__device__ __nv_bfloat16 g_h1  [(size_t)TOKENS * C_DIM];   // h1, then h2
__device__ __nv_bfloat16 g_qkv [(size_t)TOKENS * QKV_DIM];
__device__ __nv_bfloat16 g_attn[(size_t)TOKENS * C_DIM];
__device__ float         g_hmid[(size_t)TOKENS * C_DIM];
__device__ __nv_bfloat16 g_ff  [(size_t)TOKENS * FF_DIM];
// Transposed ([N,K] K-major, bf16) weights
__device__ __nv_bfloat16 g_qkvt [(size_t)QKV_DIM * C_DIM];
__device__ __nv_bfloat16 g_projt[(size_t)C_DIM * C_DIM];
__device__ __nv_bfloat16 g_mlp1t[(size_t)FF_DIM * C_DIM];
__device__ __nv_bfloat16 g_mlp2t[(size_t)C_DIM * FF_DIM];

// ---------------------------------------------------------------------------
// Helpers
// ---------------------------------------------------------------------------
__device__ __forceinline__ uint32_t smem_u32(const void* p) {
    uint32_t a;
    asm("{ .reg .u64 t; cvta.to.shared.u64 t, %1; cvt.u32.u64 %0, t; }"
        : "=r"(a) : "l"(p));
    return a;
}
#define CP_ASYNC16(dst, src) \
    asm volatile("cp.async.cg.shared.global [%0], [%1], 16;" :: "r"(dst), "l"(src))
#define CP_COMMIT() asm volatile("cp.async.commit_group;" ::: "memory")
#define CP_WAIT0()  asm volatile("cp.async.wait_group 0;" ::: "memory")

#define LDSM_X4(r0, r1, r2, r3, addr) \
    asm volatile("ldmatrix.sync.aligned.m8n8.x4.shared.b16 {%0,%1,%2,%3}, [%4];" \
        : "=r"(r0), "=r"(r1), "=r"(r2), "=r"(r3) : "r"(addr))

#define MMA_BF16(cf, av, bv) \
    asm volatile("mma.sync.aligned.m16n8k16.row.col.f32.bf16.bf16.f32 " \
        "{%0,%1,%2,%3}, {%4,%5,%6,%7}, {%8,%9}, {%0,%1,%2,%3};" \
        : "+f"((cf)[0]), "+f"((cf)[1]), "+f"((cf)[2]), "+f"((cf)[3]) \
        : "r"((av)[0]), "r"((av)[1]), "r"((av)[2]), "r"((av)[3]), \
          "r"((bv)[0]), "r"((bv)[1]))

__device__ __forceinline__ float gelu_exact(float v) {
    return 0.5f * v * (1.0f + erff(v * 0.70710678118654752440f));
}

// Fast asinh: |x| form avoids cancellation; inputs are O(1..100) so no
// overflow path needed. __logf/sqrt.approx rel err ~5e-7 << bf16 floor.
__device__ __forceinline__ float fast_asinh(float x) {
    float s = fabsf(x);
    float t = fmaf(s, s, 1.0f);
    float q;
    asm("sqrt.approx.f32 %0, %1;" : "=f"(q) : "f"(t));
    float r = __logf(s + q);
    return copysignf(r, x);
}

// ---------------------------------------------------------------------------
// Elementwise arsinh norm (x4 vectorized): y = bf16(w[c]*asinh(x)+b[c])
// ---------------------------------------------------------------------------
__global__ void __launch_bounds__(256) arsinh_norm_kernel(
    const float* __restrict__ x, const float* __restrict__ w,
    const float* __restrict__ b, __nv_bfloat16* __restrict__ y, int n4)
{
    int idx = blockIdx.x * 256 + threadIdx.x;
    if (idx < n4) {
        int c = (idx * 4) & (C_DIM - 1);
        float4 xv = *(const float4*)(x + (size_t)idx * 4);
        float4 wv = *(const float4*)(w + c);
        float4 bv = *(const float4*)(b + c);
        __nv_bfloat162 lo = __floats2bfloat162_rn(
            fmaf(wv.x, fast_asinh(xv.x), bv.x),
            fmaf(wv.y, fast_asinh(xv.y), bv.y));
        __nv_bfloat162 hi = __floats2bfloat162_rn(
            fmaf(wv.z, fast_asinh(xv.z), bv.z),
            fmaf(wv.w, fast_asinh(xv.w), bv.w));
        uint2 o;
        o.x = *(const uint32_t*)&lo;
        o.y = *(const uint32_t*)&hi;
        *(uint2*)(y + (size_t)idx * 4) = o;
    }
}

// ---------------------------------------------------------------------------
// Batched transpose of all 4 weights: W[K,N] -> Wt[N,K] bf16. 512 blocks.
// ---------------------------------------------------------------------------
__global__ void __launch_bounds__(256) transpose_all_kernel(
    const float* __restrict__ w0, const float* __restrict__ w1,
    const float* __restrict__ w2, const float* __restrict__ w3,
    __nv_bfloat16* __restrict__ o0, __nv_bfloat16* __restrict__ o1,
    __nv_bfloat16* __restrict__ o2, __nv_bfloat16* __restrict__ o3)
{
    __shared__ float t[32][33];
    int id = blockIdx.x;
    const float* in; __nv_bfloat16* out; int K, N, bx, by;
    if (id < 192)      { in = w0; out = o0; K = 256; N = 768; bx = id % 24;          by = id / 24; }
    else if (id < 256) { in = w1; out = o1; K = 256; N = 256; bx = (id - 192) % 8;   by = (id - 192) / 8; }
    else if (id < 384) { in = w2; out = o2; K = 256; N = 512; bx = (id - 256) % 16;  by = (id - 256) / 16; }
    else               { in = w3; out = o3; K = 512; N = 256; bx = (id - 384) % 8;   by = (id - 384) / 8; }
    int n0 = bx * 32, k0 = by * 32;
    int tx = threadIdx.x & 31, ty = threadIdx.x >> 5;  // 32 x 8
    #pragma unroll
    for (int i = 0; i < 4; i++)
        t[ty + i * 8][tx] = in[(size_t)(k0 + ty + i * 8) * N + n0 + tx];
    __syncthreads();
    #pragma unroll
    for (int i = 0; i < 4; i++)
        out[(size_t)(n0 + ty + i * 8) * K + k0 + tx] =
            __float2bfloat16_rn(t[tx][ty + i * 8]);
}

// ---------------------------------------------------------------------------
// bf16 mma.sync GEMM: C[M,N] = A[M,K] @ Bt[N,K]^T + bias (+gelu)(+res)
// Optional fused norm2: also writes h2 = bf16(n2w*asinh(C)+n2b).
// CTA 128x128, BK=64 (128B rows, XOR-swizzled), double-buffered cp.async,
// ldmatrix.x4 fragments, 8 warps x (32m x 64n).   [R9 mainloop — proven]
// ---------------------------------------------------------------------------
#define BM 128
#define BN 128
#define BKE 64
#define STG (BM * BKE * 2)            // 16 KB per tile
#define GEMM_SMEM (4 * STG)           // 64 KB

template<bool GELU, bool RES, bool OUTBF16, bool NORM2>
__global__ void __launch_bounds__(256, 2)
gemm_bf16_kernel(const __nv_bfloat16* __restrict__ A,
                 const __nv_bfloat16* __restrict__ Bt,
                 const float* __restrict__ bias, const float* __restrict__ res,
                 void* __restrict__ Cout,
                 const float* __restrict__ n2w, const float* __restrict__ n2b,
                 __nv_bfloat16* __restrict__ h2out,
                 int M, int N, int K)
{
    extern __shared__ char smp[];     // [2]A + [2]B = 64 KB
    const uint32_t as_base = smem_u32(smp);
    const uint32_t bs_base = as_base + 2 * STG;

    const int tid  = threadIdx.x;
    const int wid  = tid >> 5;
    const int lane = tid & 31;
    const int g    = lane >> 2;
    const int tig  = lane & 3;
    const int wm   = wid >> 1;        // rows wm*32
    const int wn   = wid & 1;         // cols wn*64
    const int bm   = blockIdx.y * BM;
    const int bn   = blockIdx.x * BN;

    const int ar  = (lane & 7) + ((lane >> 3) & 1) * 8;
    const int acb = lane >> 4;
    const int br  = (lane & 7) + ((lane >> 4) & 1) * 8;
    const int bcb = (lane >> 3) & 1;

    float c[2][8][4];
    #pragma unroll
    for (int mt = 0; mt < 2; mt++)
        #pragma unroll
        for (int nt = 0; nt < 8; nt++)
            #pragma unroll
            for (int u = 0; u < 4; u++) c[mt][nt][u] = 0.0f;

    auto load_stage = [&](int buf, int k0) {
        const uint32_t ab = as_base + buf * STG;
        const uint32_t bb = bs_base + buf * STG;
        #pragma unroll
        for (int i = 0; i < 4; i++) {
            const int id = tid + i * 256;
            const int r = id >> 3, ch = id & 7;
            const uint32_t off = (uint32_t)(r * 128 + ((ch ^ (r & 7)) << 4));
            CP_ASYNC16(ab + off, A  + (size_t)(bm + r) * K + k0 + ch * 8);
            CP_ASYNC16(bb + off, Bt + (size_t)(bn + r) * K + k0 + ch * 8);
        }
    };

    load_stage(0, 0);
    CP_COMMIT();

    const int S = K / BKE;
    for (int s = 0; s < S; s++) {
        CP_WAIT0();
        __syncthreads();
        if (s + 1 < S) { load_stage((s + 1) & 1, (s + 1) * BKE); CP_COMMIT(); }

        const uint32_t ab = as_base + (s & 1) * STG;
        const uint32_t bb = bs_base + (s & 1) * STG;

        #pragma unroll
        for (int kk = 0; kk < 4; kk++) {
            uint32_t a[2][4], b[8][2];
            #pragma unroll
            for (int mt = 0; mt < 2; mt++) {
                const int row = wm * 32 + mt * 16 + ar;
                const uint32_t ad = ab + row * 128
                    + (((2 * kk + acb) ^ (row & 7)) << 4);
                LDSM_X4(a[mt][0], a[mt][1], a[mt][2], a[mt][3], ad);
            }
            #pragma unroll
            for (int p = 0; p < 4; p++) {
                const int row = wn * 64 + p * 16 + br;
                const uint32_t bd = bb + row * 128
                    + (((2 * kk + bcb) ^ (row & 7)) << 4);
                LDSM_X4(b[2 * p][0], b[2 * p][1], b[2 * p + 1][0], b[2 * p + 1][1], bd);
            }
            #pragma unroll
            for (int mt = 0; mt < 2; mt++)
                #pragma unroll
                for (int nt = 0; nt < 8; nt++)
                    MMA_BF16(c[mt][nt], a[mt], b[nt]);
        }
        __syncthreads();
    }

    // Epilogue: bias cached once per warp
    float bv[8][2];
    #pragma unroll
    for (int nt = 0; nt < 8; nt++) {
        const int col = bn + wn * 64 + nt * 8 + tig * 2;
        float2 bb = *(const float2*)(bias + col);
        bv[nt][0] = bb.x; bv[nt][1] = bb.y;
    }

    #pragma unroll
    for (int mt = 0; mt < 2; mt++) {
        #pragma unroll
        for (int half = 0; half < 2; half++) {
            const int row = bm + wm * 32 + mt * 16 + g + half * 8;
            #pragma unroll
            for (int nt = 0; nt < 8; nt++) {
                const int col = bn + wn * 64 + nt * 8 + tig * 2;
                float v0 = c[mt][nt][half * 2 + 0] + bv[nt][0];
                float v1 = c[mt][nt][half * 2 + 1] + bv[nt][1];
                if (GELU) { v0 = gelu_exact(v0); v1 = gelu_exact(v1); }
                if (RES) {
                    float2 r = *(const float2*)(res + (size_t)row * N + col);
                    v0 += r.x; v1 += r.y;
                }
                if (OUTBF16) {
                    *(__nv_bfloat162*)((__nv_bfloat16*)Cout + (size_t)row * N + col)
                        = __floats2bfloat162_rn(v0, v1);
                } else {
                    *(float2*)((float*)Cout + (size_t)row * N + col)
                        = make_float2(v0, v1);
                }
                if (NORM2) {
                    float h0  = fmaf(n2w[col],     fast_asinh(v0), n2b[col]);
                    float h1v = fmaf(n2w[col + 1], fast_asinh(v1), n2b[col + 1]);
                    *(__nv_bfloat162*)(h2out + (size_t)row * N + col)
                        = __floats2bfloat162_rn(h0, h1v);
                }
            }
        }
    }
}

// ---------------------------------------------------------------------------
// NATTEN 3x3, smem-tiled: CTA = 8 consecutive tokens in one image row
// (8 warps, warp w -> token j0*8+w). The union of their 3x3 windows is a
// 3-row x 10-col halo of k/v, cp.async'ed into smem once and reused by all
// warps. Per-head 4-lane groups with 2-shfl dot reduction (as before).
// ---------------------------------------------------------------------------
#define NAT_COLS 10
#define NAT_ROWB (NAT_COLS * C_DIM * 2)          // bytes per halo row: 5120
#define NAT_TILE (3 * NAT_ROWB)                  // 15360 B per tensor

__global__ void __launch_bounds__(256) natten_kernel(
    const __nv_bfloat16* __restrict__ qkv, __nv_bfloat16* __restrict__ out)
{
    __shared__ __align__(16) char halo[2 * NAT_TILE];   // k then v, 30 KB
    const uint32_t kb = smem_u32(halo);
    const uint32_t vb = kb + NAT_TILE;

    const int tid  = threadIdx.x;
    const int wid  = tid >> 5;          // warp -> token within group
    const int lane = tid & 31;
    const int c0   = lane * 8;

    const int blk = blockIdx.x;         // b*512 + i*8 + j0
    const int b   = blk >> 9;
    const int i   = (blk >> 3) & 63;
    const int j0  = blk & 7;

    const int ri    = min(max(i - 1, 0), 61);              // top halo row
    const int cbase = max(0, min(j0 * 8 - 1, 64 - NAT_COLS)); // left halo col

    // Cooperative halo load: 2 tensors x 3 rows x 10 cols x 512 B
    // = 1920 16B chunks over 256 threads.
    {
        const size_t rowbase = ((size_t)(b << 6) + ri) * 64 + cbase;
        for (int ci = tid; ci < 1920; ci += 256) {
            const int tv  = ci >= 960;            // 0 = k, 1 = v
            const int cc  = tv ? ci - 960 : ci;   // 0..959
            const int rc  = cc >> 5;              // (row, col) index 0..29
            const int chk = cc & 31;              // 16B chunk within 512B
            const int r   = rc / NAT_COLS;
            const int col = rc - r * NAT_COLS;
            const __nv_bfloat16* src = qkv
                + (rowbase + (size_t)r * 64 + col) * QKV_DIM
                + (tv ? 512 : 256) + chk * 8;
            CP_ASYNC16((tv ? vb : kb) + (uint32_t)(rc * 512 + chk * 16), src);
        }
    }
    CP_COMMIT();

    // q for this warp's token (global load, unique per warp)
    const int j     = j0 * 8 + wid;
    const int token = ((b << 6) + i) * 64 + j;
    float q[8];
    {
        uint4 qp = *(const uint4*)(qkv + (size_t)token * QKV_DIM + c0);
        const uint32_t* qu = (const uint32_t*)&qp;
        const float scale = 0.17677669529663687f;  // 1/sqrt(32)
        #pragma unroll
        for (int u = 0; u < 4; u++) {
            float2 f = __bfloat1622float2(*(const __nv_bfloat162*)&qu[u]);
            q[2 * u]     = f.x * scale;
            q[2 * u + 1] = f.y * scale;
        }
    }

    const int lc = min(max(j - 1, 0), 61) - cbase;   // 0..7
    CP_WAIT0();
    __syncthreads();

    // Scores
    float s[9];
    #pragma unroll
    for (int m = 0; m < 9; m++) {
        const int mr = m / 3, mc = lc + m % 3;
        uint4 kp;
        asm volatile("ld.shared.v4.u32 {%0,%1,%2,%3}, [%4];"
            : "=r"(kp.x), "=r"(kp.y), "=r"(kp.z), "=r"(kp.w)
            : "r"(kb + (uint32_t)((mr * NAT_COLS + mc) * 512 + lane * 16)));
        const uint32_t* ku = (const uint32_t*)&kp;
        float dot = 0.0f;
        #pragma unroll
        for (int u = 0; u < 4; u++) {
            float2 f = __bfloat1622float2(*(const __nv_bfloat162*)&ku[u]);
            dot = fmaf(q[2 * u], f.x, dot);
            dot = fmaf(q[2 * u + 1], f.y, dot);
        }
        dot += __shfl_xor_sync(0xffffffffu, dot, 1);
        dot += __shfl_xor_sync(0xffffffffu, dot, 2);
        s[m] = dot;
    }

    float mx = s[0];
    #pragma unroll
    for (int m = 1; m < 9; m++) mx = fmaxf(mx, s[m]);
    float sum = 0.0f;
    #pragma unroll
    for (int m = 0; m < 9; m++) { s[m] = __expf(s[m] - mx); sum += s[m]; }
    const float inv = 1.0f / sum;

    // Accumulate from smem v
    float o[8];
    #pragma unroll
    for (int u = 0; u < 8; u++) o[u] = 0.0f;
    #pragma unroll
    for (int m = 0; m < 9; m++) {
        const int mr = m / 3, mc = lc + m % 3;
        uint4 vp;
        asm volatile("ld.shared.v4.u32 {%0,%1,%2,%3}, [%4];"
            : "=r"(vp.x), "=r"(vp.y), "=r"(vp.z), "=r"(vp.w)
            : "r"(vb + (uint32_t)((mr * NAT_COLS + mc) * 512 + lane * 16)));
        const uint32_t* vu = (const uint32_t*)&vp;
        #pragma unroll
        for (int u = 0; u < 4; u++) {
            float2 f = __bfloat1622float2(*(const __nv_bfloat162*)&vu[u]);
            o[2 * u]     = fmaf(s[m], f.x, o[2 * u]);
            o[2 * u + 1] = fmaf(s[m], f.y, o[2 * u + 1]);
        }
    }

    uint4 op;
    uint32_t* ou = (uint32_t*)&op;
    #pragma unroll
    for (int u = 0; u < 4; u++) {
        __nv_bfloat162 p = __floats2bfloat162_rn(o[2 * u] * inv, o[2 * u + 1] * inv);
        ou[u] = *(const uint32_t*)&p;
    }
    *(uint4*)(out + (size_t)token * C_DIM + c0) = op;
}

// ---------------------------------------------------------------------------
// Launcher
// ---------------------------------------------------------------------------
extern "C" void kernel_launch(void* const* d_in, const int* in_sizes, int n_in,
                              void* d_out, int out_size)
{
    (void)in_sizes; (void)n_in; (void)out_size;
    const float* h      = (const float*)d_in[0];
    const float* qkv_w  = (const float*)d_in[1];
    const float* qkv_b  = (const float*)d_in[2];
    const float* proj_w = (const float*)d_in[3];
    const float* proj_b = (const float*)d_in[4];
    const float* n1_w   = (const float*)d_in[5];
    const float* n1_b   = (const float*)d_in[6];
    const float* n2_w   = (const float*)d_in[7];
    const float* n2_b   = (const float*)d_in[8];
    const float* mlp_w1 = (const float*)d_in[9];
    const float* mlp_b1 = (const float*)d_in[10];
    const float* mlp_w2 = (const float*)d_in[11];
    const float* mlp_b2 = (const float*)d_in[12];
    float* out = (float*)d_out;

    __nv_bfloat16 *h1, *qkv, *attn, *ff, *qkvt, *projt, *mlp1t, *mlp2t;
    float *hmid;
    cudaGetSymbolAddress((void**)&h1,    g_h1);
    cudaGetSymbolAddress((void**)&qkv,   g_qkv);
    cudaGetSymbolAddress((void**)&attn,  g_attn);
    cudaGetSymbolAddress((void**)&hmid,  g_hmid);
    cudaGetSymbolAddress((void**)&ff,    g_ff);
    cudaGetSymbolAddress((void**)&qkvt,  g_qkvt);
    cudaGetSymbolAddress((void**)&projt, g_projt);
    cudaGetSymbolAddress((void**)&mlp1t, g_mlp1t);
    cudaGetSymbolAddress((void**)&mlp2t, g_mlp2t);

    cudaFuncSetAttribute(gemm_bf16_kernel<false, false, true,  false>,
                         cudaFuncAttributeMaxDynamicSharedMemorySize, GEMM_SMEM);
    cudaFuncSetAttribute(gemm_bf16_kernel<false, true,  false, true>,
                         cudaFuncAttributeMaxDynamicSharedMemorySize, GEMM_SMEM);
    cudaFuncSetAttribute(gemm_bf16_kernel<true,  false, true,  false>,
                         cudaFuncAttributeMaxDynamicSharedMemorySize, GEMM_SMEM);
    cudaFuncSetAttribute(gemm_bf16_kernel<false, true,  false, false>,
                         cudaFuncAttributeMaxDynamicSharedMemorySize, GEMM_SMEM);

    const int M = TOKENS;
    const int nElem = TOKENS * C_DIM;

    // Weight transposes (bf16), one launch
    transpose_all_kernel<<<512, 256>>>(qkv_w, proj_w, mlp_w1, mlp_w2,
                                       qkvt, projt, mlp1t, mlp2t);

    // 1. h1 = bf16(arsinh_norm(h; n1))   (x4 vectorized)
    arsinh_norm_kernel<<<(nElem / 4 + 255) / 256, 256>>>(h, n1_w, n1_b, h1, nElem / 4);

    // 2. qkv = h1 @ qkv_w + qkv_b   (bf16 out)
    gemm_bf16_kernel<false, false, true, false>
        <<<dim3(QKV_DIM / BN, M / BM), 256, GEMM_SMEM>>>(
        h1, qkvt, qkv_b, nullptr, qkv, nullptr, nullptr, nullptr,
        M, QKV_DIM, C_DIM);

    // 3. NATTEN attention (smem-tiled halo), 8 tokens per CTA
    natten_kernel<<<TOKENS / 8, 256>>>(qkv, attn);

    // 4. hmid = h + attn @ proj_w + proj_b  (fp32) ; fused h2 = norm2(hmid) bf16
    gemm_bf16_kernel<false, true, false, true>
        <<<dim3(C_DIM / BN, M / BM), 256, GEMM_SMEM>>>(
        attn, projt, proj_b, h, hmid, n2_w, n2_b, h1,
        M, C_DIM, C_DIM);

    // 5. ff = bf16(gelu(h2 @ mlp_w1 + mlp_b1))
    gemm_bf16_kernel<true, false, true, false>
        <<<dim3(FF_DIM / BN, M / BM), 256, GEMM_SMEM>>>(
        h1, mlp1t, mlp_b1, nullptr, ff, nullptr, nullptr, nullptr,
        M, FF_DIM, C_DIM);

    // 6. out = hmid + ff @ mlp_w2 + mlp_b2  (fp32)
    gemm_bf16_kernel<false, true, false, false>
        <<<dim3(C_DIM / BN, M / BM), 256, GEMM_SMEM>>>(
        ff, mlp2t, mlp_b2, hmid, out, nullptr, nullptr, nullptr,
        M, C_DIM, FF_DIM);
}

// round 14
// speedup vs baseline: 1.0846x; 1.0846x over previous
#include <cuda_runtime.h>
#include <cuda_bf16.h>
#include <cstdint>

// ---------------------------------------------------------------------------
// LocalAttentionBlock on GB300 (base sm_103 target): bf16 mma.sync m16n8k16
// GEMMs (32x64 warp tiles, double-buffered cp.async, 1 barrier/stage) +
// warp-per-token NATTEN (two-pass v), norm2 fused into proj epilogue,
// fast MUFU-based asinh.
// B=16, H=W=64, C=256, heads=8, hd=32
// ---------------------------------------------------------------------------

#define TOKENS   65536
#define C_DIM    256
#define QKV_DIM  768
#define FF_DIM   512
#define NHEADS   8
#define HDIM     32

// Scratch (device globals — allocation-free rule)
__device__ __nv_bfloat16 g_h1  [(size_t)TOKENS * C_DIM];   // h1, then h2
__device__ __nv_bfloat16 g_qkv [(size_t)TOKENS * QKV_DIM];
__device__ __nv_bfloat16 g_attn[(size_t)TOKENS * C_DIM];
__device__ float         g_hmid[(size_t)TOKENS * C_DIM];
__device__ __nv_bfloat16 g_ff  [(size_t)TOKENS * FF_DIM];
// Transposed ([N,K] K-major, bf16) weights
__device__ __nv_bfloat16 g_qkvt [(size_t)QKV_DIM * C_DIM];
__device__ __nv_bfloat16 g_projt[(size_t)C_DIM * C_DIM];
__device__ __nv_bfloat16 g_mlp1t[(size_t)FF_DIM * C_DIM];
__device__ __nv_bfloat16 g_mlp2t[(size_t)C_DIM * FF_DIM];

// ---------------------------------------------------------------------------
// Helpers
// ---------------------------------------------------------------------------
__device__ __forceinline__ uint32_t smem_u32(const void* p) {
    uint32_t a;
    asm("{ .reg .u64 t; cvta.to.shared.u64 t, %1; cvt.u32.u64 %0, t; }"
        : "=r"(a) : "l"(p));
    return a;
}
#define CP_ASYNC16(dst, src) \
    asm volatile("cp.async.cg.shared.global [%0], [%1], 16;" :: "r"(dst), "l"(src))
#define CP_COMMIT() asm volatile("cp.async.commit_group;" ::: "memory")
#define CP_WAIT0()  asm volatile("cp.async.wait_group 0;" ::: "memory")

#define LDSM_X4(r0, r1, r2, r3, addr) \
    asm volatile("ldmatrix.sync.aligned.m8n8.x4.shared.b16 {%0,%1,%2,%3}, [%4];" \
        : "=r"(r0), "=r"(r1), "=r"(r2), "=r"(r3) : "r"(addr))

#define MMA_BF16(cf, av, bv) \
    asm volatile("mma.sync.aligned.m16n8k16.row.col.f32.bf16.bf16.f32 " \
        "{%0,%1,%2,%3}, {%4,%5,%6,%7}, {%8,%9}, {%0,%1,%2,%3};" \
        : "+f"((cf)[0]), "+f"((cf)[1]), "+f"((cf)[2]), "+f"((cf)[3]) \
        : "r"((av)[0]), "r"((av)[1]), "r"((av)[2]), "r"((av)[3]), \
          "r"((bv)[0]), "r"((bv)[1]))

__device__ __forceinline__ float gelu_exact(float v) {
    return 0.5f * v * (1.0f + erff(v * 0.70710678118654752440f));
}

// Fast asinh: |x| form avoids cancellation; inputs are O(1..100) so no
// overflow path needed. __logf/sqrt.approx rel err ~5e-7 << bf16 floor.
__device__ __forceinline__ float fast_asinh(float x) {
    float s = fabsf(x);
    float t = fmaf(s, s, 1.0f);
    float q;
    asm("sqrt.approx.f32 %0, %1;" : "=f"(q) : "f"(t));
    float r = __logf(s + q);
    return copysignf(r, x);
}

// ---------------------------------------------------------------------------
// Elementwise arsinh norm (x4 vectorized): y = bf16(w[c]*asinh(x)+b[c])
// ---------------------------------------------------------------------------
__global__ void __launch_bounds__(256) arsinh_norm_kernel(
    const float* __restrict__ x, const float* __restrict__ w,
    const float* __restrict__ b, __nv_bfloat16* __restrict__ y, int n4)
{
    int idx = blockIdx.x * 256 + threadIdx.x;
    if (idx < n4) {
        int c = (idx * 4) & (C_DIM - 1);
        float4 xv = *(const float4*)(x + (size_t)idx * 4);
        float4 wv = *(const float4*)(w + c);
        float4 bv = *(const float4*)(b + c);
        __nv_bfloat162 lo = __floats2bfloat162_rn(
            fmaf(wv.x, fast_asinh(xv.x), bv.x),
            fmaf(wv.y, fast_asinh(xv.y), bv.y));
        __nv_bfloat162 hi = __floats2bfloat162_rn(
            fmaf(wv.z, fast_asinh(xv.z), bv.z),
            fmaf(wv.w, fast_asinh(xv.w), bv.w));
        uint2 o;
        o.x = *(const uint32_t*)&lo;
        o.y = *(const uint32_t*)&hi;
        *(uint2*)(y + (size_t)idx * 4) = o;
    }
}

// ---------------------------------------------------------------------------
// Batched transpose of all 4 weights: W[K,N] -> Wt[N,K] bf16. 512 blocks.
// ---------------------------------------------------------------------------
__global__ void __launch_bounds__(256) transpose_all_kernel(
    const float* __restrict__ w0, const float* __restrict__ w1,
    const float* __restrict__ w2, const float* __restrict__ w3,
    __nv_bfloat16* __restrict__ o0, __nv_bfloat16* __restrict__ o1,
    __nv_bfloat16* __restrict__ o2, __nv_bfloat16* __restrict__ o3)
{
    __shared__ float t[32][33];
    int id = blockIdx.x;
    const float* in; __nv_bfloat16* out; int K, N, bx, by;
    if (id < 192)      { in = w0; out = o0; K = 256; N = 768; bx = id % 24;          by = id / 24; }
    else if (id < 256) { in = w1; out = o1; K = 256; N = 256; bx = (id - 192) % 8;   by = (id - 192) / 8; }
    else if (id < 384) { in = w2; out = o2; K = 256; N = 512; bx = (id - 256) % 16;  by = (id - 256) / 16; }
    else               { in = w3; out = o3; K = 512; N = 256; bx = (id - 384) % 8;   by = (id - 384) / 8; }
    int n0 = bx * 32, k0 = by * 32;
    int tx = threadIdx.x & 31, ty = threadIdx.x >> 5;  // 32 x 8
    #pragma unroll
    for (int i = 0; i < 4; i++)
        t[ty + i * 8][tx] = in[(size_t)(k0 + ty + i * 8) * N + n0 + tx];
    __syncthreads();
    #pragma unroll
    for (int i = 0; i < 4; i++)
        out[(size_t)(n0 + ty + i * 8) * K + k0 + tx] =
            __float2bfloat16_rn(t[tx][ty + i * 8]);
}

// ---------------------------------------------------------------------------
// bf16 mma.sync GEMM: C[M,N] = A[M,K] @ Bt[N,K]^T + bias (+gelu)(+res)
// Optional fused norm2: also writes h2 = bf16(n2w*asinh(C)+n2b).
// CTA 128x128, BK=64 (128B rows, XOR-swizzled), double-buffered cp.async,
// ldmatrix.x4 fragments, 8 warps x (32m x 64n), ONE barrier per stage
// (top barrier of iter s+1 already orders reads of buf s%2 before the
//  stage-s+2 prefetch that overwrites it).
// ---------------------------------------------------------------------------
#define BM 128
#define BN 128
#define BKE 64
#define STG (BM * BKE * 2)            // 16 KB per tile
#define GEMM_SMEM (4 * STG)           // 64 KB

template<bool GELU, bool RES, bool OUTBF16, bool NORM2>
__global__ void __launch_bounds__(256, 2)
gemm_bf16_kernel(const __nv_bfloat16* __restrict__ A,
                 const __nv_bfloat16* __restrict__ Bt,
                 const float* __restrict__ bias, const float* __restrict__ res,
                 void* __restrict__ Cout,
                 const float* __restrict__ n2w, const float* __restrict__ n2b,
                 __nv_bfloat16* __restrict__ h2out,
                 int M, int N, int K)
{
    extern __shared__ char smp[];     // [2]A + [2]B = 64 KB
    const uint32_t as_base = smem_u32(smp);
    const uint32_t bs_base = as_base + 2 * STG;

    const int tid  = threadIdx.x;
    const int wid  = tid >> 5;
    const int lane = tid & 31;
    const int g    = lane >> 2;
    const int tig  = lane & 3;
    const int wm   = wid >> 1;        // rows wm*32
    const int wn   = wid & 1;         // cols wn*64
    const int bm   = blockIdx.y * BM;
    const int bn   = blockIdx.x * BN;

    const int ar  = (lane & 7) + ((lane >> 3) & 1) * 8;
    const int acb = lane >> 4;
    const int br  = (lane & 7) + ((lane >> 4) & 1) * 8;
    const int bcb = (lane >> 3) & 1;

    float c[2][8][4];
    #pragma unroll
    for (int mt = 0; mt < 2; mt++)
        #pragma unroll
        for (int nt = 0; nt < 8; nt++)
            #pragma unroll
            for (int u = 0; u < 4; u++) c[mt][nt][u] = 0.0f;

    auto load_stage = [&](int buf, int k0) {
        const uint32_t ab = as_base + buf * STG;
        const uint32_t bb = bs_base + buf * STG;
        #pragma unroll
        for (int i = 0; i < 4; i++) {
            const int id = tid + i * 256;
            const int r = id >> 3, ch = id & 7;
            const uint32_t off = (uint32_t)(r * 128 + ((ch ^ (r & 7)) << 4));
            CP_ASYNC16(ab + off, A  + (size_t)(bm + r) * K + k0 + ch * 8);
            CP_ASYNC16(bb + off, Bt + (size_t)(bn + r) * K + k0 + ch * 8);
        }
    };

    load_stage(0, 0);
    CP_COMMIT();

    const int S = K / BKE;
    for (int s = 0; s < S; s++) {
        CP_WAIT0();
        __syncthreads();              // data visible + prior reads of this buf done
        if (s + 1 < S) { load_stage((s + 1) & 1, (s + 1) * BKE); CP_COMMIT(); }

        const uint32_t ab = as_base + (s & 1) * STG;
        const uint32_t bb = bs_base + (s & 1) * STG;

        #pragma unroll
        for (int kk = 0; kk < 4; kk++) {
            uint32_t a[2][4], b[8][2];
            #pragma unroll
            for (int mt = 0; mt < 2; mt++) {
                const int row = wm * 32 + mt * 16 + ar;
                const uint32_t ad = ab + row * 128
                    + (((2 * kk + acb) ^ (row & 7)) << 4);
                LDSM_X4(a[mt][0], a[mt][1], a[mt][2], a[mt][3], ad);
            }
            #pragma unroll
            for (int p = 0; p < 4; p++) {
                const int row = wn * 64 + p * 16 + br;
                const uint32_t bd = bb + row * 128
                    + (((2 * kk + bcb) ^ (row & 7)) << 4);
                LDSM_X4(b[2 * p][0], b[2 * p][1], b[2 * p + 1][0], b[2 * p + 1][1], bd);
            }
            #pragma unroll
            for (int mt = 0; mt < 2; mt++)
                #pragma unroll
                for (int nt = 0; nt < 8; nt++)
                    MMA_BF16(c[mt][nt], a[mt], b[nt]);
        }
        // no trailing barrier: next iteration's top barrier provides the
        // read-before-overwrite ordering for this buffer.
    }

    // Epilogue: bias cached once per warp
    float bv[8][2];
    #pragma unroll
    for (int nt = 0; nt < 8; nt++) {
        const int col = bn + wn * 64 + nt * 8 + tig * 2;
        float2 bb = *(const float2*)(bias + col);
        bv[nt][0] = bb.x; bv[nt][1] = bb.y;
    }

    #pragma unroll
    for (int mt = 0; mt < 2; mt++) {
        #pragma unroll
        for (int half = 0; half < 2; half++) {
            const int row = bm + wm * 32 + mt * 16 + g + half * 8;
            #pragma unroll
            for (int nt = 0; nt < 8; nt++) {
                const int col = bn + wn * 64 + nt * 8 + tig * 2;
                float v0 = c[mt][nt][half * 2 + 0] + bv[nt][0];
                float v1 = c[mt][nt][half * 2 + 1] + bv[nt][1];
                if (GELU) { v0 = gelu_exact(v0); v1 = gelu_exact(v1); }
                if (RES) {
                    float2 r = *(const float2*)(res + (size_t)row * N + col);
                    v0 += r.x; v1 += r.y;
                }
                if (OUTBF16) {
                    *(__nv_bfloat162*)((__nv_bfloat16*)Cout + (size_t)row * N + col)
                        = __floats2bfloat162_rn(v0, v1);
                } else {
                    *(float2*)((float*)Cout + (size_t)row * N + col)
                        = make_float2(v0, v1);
                }
                if (NORM2) {
                    float h0  = fmaf(n2w[col],     fast_asinh(v0), n2b[col]);
                    float h1v = fmaf(n2w[col + 1], fast_asinh(v1), n2b[col + 1]);
                    *(__nv_bfloat162*)(h2out + (size_t)row * N + col)
                        = __floats2bfloat162_rn(h0, h1v);
                }
            }
        }
    }
}

// ---------------------------------------------------------------------------
// NATTEN 3x3: ONE warp per token, all 8 heads. Lane owns 8 contiguous
// channels; each head = one 4-lane group (2-shfl dot reduction).
// Two-pass: k loads in the score pass, v loads deferred to the accumulate
// pass (drops the 36-reg vv[9] cache -> higher occupancy; same LDG count).
// ---------------------------------------------------------------------------
__global__ void __launch_bounds__(256) natten_kernel(
    const __nv_bfloat16* __restrict__ qkv, __nv_bfloat16* __restrict__ out)
{
    const int token = (blockIdx.x * 256 + threadIdx.x) >> 5;
    const int lane  = threadIdx.x & 31;
    const int c0    = lane * 8;
    const int b = token >> 12;
    const int i = (token >> 6) & 63;
    const int j = token & 63;

    const float scale = 0.17677669529663687f;  // 1/sqrt(32)

    float q[8];
    {
        uint4 qp = *(const uint4*)(qkv + (size_t)token * QKV_DIM + c0);
        const uint32_t* qu = (const uint32_t*)&qp;
        #pragma unroll
        for (int u = 0; u < 4; u++) {
            float2 f = __bfloat1622float2(*(const __nv_bfloat162*)&qu[u]);
            q[2 * u]     = f.x * scale;
            q[2 * u + 1] = f.y * scale;
        }
    }

    const int ri = min(max(i - 1, 0), 61);
    const int ci = min(max(j - 1, 0), 61);
    const size_t nbase = ((size_t)(b << 6) + ri) * 64 + ci;   // top-left token

    // Pass 1: scores (k only)
    float s[9];
    #pragma unroll
    for (int m = 0; m < 9; m++) {
        const size_t nt = (nbase + (size_t)(m / 3) * 64 + (m % 3)) * QKV_DIM;
        uint4 kp = *(const uint4*)(qkv + nt + 256 + c0);
        const uint32_t* ku = (const uint32_t*)&kp;
        float dot = 0.0f;
        #pragma unroll
        for (int u = 0; u < 4; u++) {
            float2 f = __bfloat1622float2(*(const __nv_bfloat162*)&ku[u]);
            dot = fmaf(q[2 * u], f.x, dot);
            dot = fmaf(q[2 * u + 1], f.y, dot);
        }
        dot += __shfl_xor_sync(0xffffffffu, dot, 1);
        dot += __shfl_xor_sync(0xffffffffu, dot, 2);
        s[m] = dot;
    }

    float mx = s[0];
    #pragma unroll
    for (int m = 1; m < 9; m++) mx = fmaxf(mx, s[m]);
    float sum = 0.0f;
    #pragma unroll
    for (int m = 0; m < 9; m++) { s[m] = __expf(s[m] - mx); sum += s[m]; }
    const float inv = 1.0f / sum;

    // Pass 2: accumulate (v loaded lazily)
    float o[8];
    #pragma unroll
    for (int u = 0; u < 8; u++) o[u] = 0.0f;
    #pragma unroll
    for (int m = 0; m < 9; m++) {
        const size_t nt = (nbase + (size_t)(m / 3) * 64 + (m % 3)) * QKV_DIM;
        uint4 vp = *(const uint4*)(qkv + nt + 512 + c0);
        const uint32_t* vu = (const uint32_t*)&vp;
        #pragma unroll
        for (int u = 0; u < 4; u++) {
            float2 f = __bfloat1622float2(*(const __nv_bfloat162*)&vu[u]);
            o[2 * u]     = fmaf(s[m], f.x, o[2 * u]);
            o[2 * u + 1] = fmaf(s[m], f.y, o[2 * u + 1]);
        }
    }

    uint4 op;
    uint32_t* ou = (uint32_t*)&op;
    #pragma unroll
    for (int u = 0; u < 4; u++) {
        __nv_bfloat162 p = __floats2bfloat162_rn(o[2 * u] * inv, o[2 * u + 1] * inv);
        ou[u] = *(const uint32_t*)&p;
    }
    *(uint4*)(out + (size_t)token * C_DIM + c0) = op;
}

// ---------------------------------------------------------------------------
// Launcher
// ---------------------------------------------------------------------------
extern "C" void kernel_launch(void* const* d_in, const int* in_sizes, int n_in,
                              void* d_out, int out_size)
{
    (void)in_sizes; (void)n_in; (void)out_size;
    const float* h      = (const float*)d_in[0];
    const float* qkv_w  = (const float*)d_in[1];
    const float* qkv_b  = (const float*)d_in[2];
    const float* proj_w = (const float*)d_in[3];
    const float* proj_b = (const float*)d_in[4];
    const float* n1_w   = (const float*)d_in[5];
    const float* n1_b   = (const float*)d_in[6];
    const float* n2_w   = (const float*)d_in[7];
    const float* n2_b   = (const float*)d_in[8];
    const float* mlp_w1 = (const float*)d_in[9];
    const float* mlp_b1 = (const float*)d_in[10];
    const float* mlp_w2 = (const float*)d_in[11];
    const float* mlp_b2 = (const float*)d_in[12];
    float* out = (float*)d_out;

    __nv_bfloat16 *h1, *qkv, *attn, *ff, *qkvt, *projt, *mlp1t, *mlp2t;
    float *hmid;
    cudaGetSymbolAddress((void**)&h1,    g_h1);
    cudaGetSymbolAddress((void**)&qkv,   g_qkv);
    cudaGetSymbolAddress((void**)&attn,  g_attn);
    cudaGetSymbolAddress((void**)&hmid,  g_hmid);
    cudaGetSymbolAddress((void**)&ff,    g_ff);
    cudaGetSymbolAddress((void**)&qkvt,  g_qkvt);
    cudaGetSymbolAddress((void**)&projt, g_projt);
    cudaGetSymbolAddress((void**)&mlp1t, g_mlp1t);
    cudaGetSymbolAddress((void**)&mlp2t, g_mlp2t);

    cudaFuncSetAttribute(gemm_bf16_kernel<false, false, true,  false>,
                         cudaFuncAttributeMaxDynamicSharedMemorySize, GEMM_SMEM);
    cudaFuncSetAttribute(gemm_bf16_kernel<false, true,  false, true>,
                         cudaFuncAttributeMaxDynamicSharedMemorySize, GEMM_SMEM);
    cudaFuncSetAttribute(gemm_bf16_kernel<true,  false, true,  false>,
                         cudaFuncAttributeMaxDynamicSharedMemorySize, GEMM_SMEM);
    cudaFuncSetAttribute(gemm_bf16_kernel<false, true,  false, false>,
                         cudaFuncAttributeMaxDynamicSharedMemorySize, GEMM_SMEM);

    const int M = TOKENS;
    const int nElem = TOKENS * C_DIM;

    // Weight transposes (bf16), one launch
    transpose_all_kernel<<<512, 256>>>(qkv_w, proj_w, mlp_w1, mlp_w2,
                                       qkvt, projt, mlp1t, mlp2t);

    // 1. h1 = bf16(arsinh_norm(h; n1))   (x4 vectorized)
    arsinh_norm_kernel<<<(nElem / 4 + 255) / 256, 256>>>(h, n1_w, n1_b, h1, nElem / 4);

    // 2. qkv = h1 @ qkv_w + qkv_b   (bf16 out)
    gemm_bf16_kernel<false, false, true, false>
        <<<dim3(QKV_DIM / BN, M / BM), 256, GEMM_SMEM>>>(
        h1, qkvt, qkv_b, nullptr, qkv, nullptr, nullptr, nullptr,
        M, QKV_DIM, C_DIM);

    // 3. NATTEN attention (two-pass v), 1 warp per token
    natten_kernel<<<TOKENS / 8, 256>>>(qkv, attn);

    // 4. hmid = h + attn @ proj_w + proj_b  (fp32) ; fused h2 = norm2(hmid) bf16
    gemm_bf16_kernel<false, true, false, true>
        <<<dim3(C_DIM / BN, M / BM), 256, GEMM_SMEM>>>(
        attn, projt, proj_b, h, hmid, n2_w, n2_b, h1,
        M, C_DIM, C_DIM);

    // 5. ff = bf16(gelu(h2 @ mlp_w1 + mlp_b1))
    gemm_bf16_kernel<true, false, true, false>
        <<<dim3(FF_DIM / BN, M / BM), 256, GEMM_SMEM>>>(
        h1, mlp1t, mlp_b1, nullptr, ff, nullptr, nullptr, nullptr,
        M, FF_DIM, C_DIM);

    // 6. out = hmid + ff @ mlp_w2 + mlp_b2  (fp32)
    gemm_bf16_kernel<false, true, false, false>
        <<<dim3(C_DIM / BN, M / BM), 256, GEMM_SMEM>>>(
        ff, mlp2t, mlp_b2, hmid, out, nullptr, nullptr, nullptr,
        M, C_DIM, FF_DIM);
}

// round 15
// speedup vs baseline: 1.5802x; 1.4570x over previous
#include <cuda_runtime.h>
#include <cuda_bf16.h>
#include <cstdint>

// ---------------------------------------------------------------------------
// LocalAttentionBlock on GB300 (base sm_103 target): bf16 mma.sync m16n8k16
// GEMMs (32x64 warp tiles, double-buffered cp.async) + warp-per-token NATTEN,
// norm2 fused into proj epilogue, fast MUFU-based asinh.
// [R12 configuration — best measured — with natten occupancy cap (256,5)]
// B=16, H=W=64, C=256, heads=8, hd=32
// ---------------------------------------------------------------------------

#define TOKENS   65536
#define C_DIM    256
#define QKV_DIM  768
#define FF_DIM   512
#define NHEADS   8
#define HDIM     32

// Scratch (device globals — allocation-free rule)
__device__ __nv_bfloat16 g_h1  [(size_t)TOKENS * C_DIM];   // h1, then h2
__device__ __nv_bfloat16 g_qkv [(size_t)TOKENS * QKV_DIM];
__device__ __nv_bfloat16 g_attn[(size_t)TOKENS * C_DIM];
__device__ float         g_hmid[(size_t)TOKENS * C_DIM];
__device__ __nv_bfloat16 g_ff  [(size_t)TOKENS * FF_DIM];
// Transposed ([N,K] K-major, bf16) weights
__device__ __nv_bfloat16 g_qkvt [(size_t)QKV_DIM * C_DIM];
__device__ __nv_bfloat16 g_projt[(size_t)C_DIM * C_DIM];
__device__ __nv_bfloat16 g_mlp1t[(size_t)FF_DIM * C_DIM];
__device__ __nv_bfloat16 g_mlp2t[(size_t)C_DIM * FF_DIM];

// ---------------------------------------------------------------------------
// Helpers
// ---------------------------------------------------------------------------
__device__ __forceinline__ uint32_t smem_u32(const void* p) {
    uint32_t a;
    asm("{ .reg .u64 t; cvta.to.shared.u64 t, %1; cvt.u32.u64 %0, t; }"
        : "=r"(a) : "l"(p));
    return a;
}
#define CP_ASYNC16(dst, src) \
    asm volatile("cp.async.cg.shared.global [%0], [%1], 16;" :: "r"(dst), "l"(src))
#define CP_COMMIT() asm volatile("cp.async.commit_group;" ::: "memory")
#define CP_WAIT0()  asm volatile("cp.async.wait_group 0;" ::: "memory")

#define LDSM_X4(r0, r1, r2, r3, addr) \
    asm volatile("ldmatrix.sync.aligned.m8n8.x4.shared.b16 {%0,%1,%2,%3}, [%4];" \
        : "=r"(r0), "=r"(r1), "=r"(r2), "=r"(r3) : "r"(addr))

#define MMA_BF16(cf, av, bv) \
    asm volatile("mma.sync.aligned.m16n8k16.row.col.f32.bf16.bf16.f32 " \
        "{%0,%1,%2,%3}, {%4,%5,%6,%7}, {%8,%9}, {%0,%1,%2,%3};" \
        : "+f"((cf)[0]), "+f"((cf)[1]), "+f"((cf)[2]), "+f"((cf)[3]) \
        : "r"((av)[0]), "r"((av)[1]), "r"((av)[2]), "r"((av)[3]), \
          "r"((bv)[0]), "r"((bv)[1]))

__device__ __forceinline__ float gelu_exact(float v) {
    return 0.5f * v * (1.0f + erff(v * 0.70710678118654752440f));
}

// Fast asinh: |x| form avoids cancellation; inputs are O(1..100) so no
// overflow path needed. __logf/sqrt.approx rel err ~5e-7 << bf16 floor.
__device__ __forceinline__ float fast_asinh(float x) {
    float s = fabsf(x);
    float t = fmaf(s, s, 1.0f);
    float q;
    asm("sqrt.approx.f32 %0, %1;" : "=f"(q) : "f"(t));
    float r = __logf(s + q);
    return copysignf(r, x);
}

// ---------------------------------------------------------------------------
// Elementwise arsinh norm (x4 vectorized): y = bf16(w[c]*asinh(x)+b[c])
// ---------------------------------------------------------------------------
__global__ void __launch_bounds__(256) arsinh_norm_kernel(
    const float* __restrict__ x, const float* __restrict__ w,
    const float* __restrict__ b, __nv_bfloat16* __restrict__ y, int n4)
{
    int idx = blockIdx.x * 256 + threadIdx.x;
    if (idx < n4) {
        int c = (idx * 4) & (C_DIM - 1);
        float4 xv = *(const float4*)(x + (size_t)idx * 4);
        float4 wv = *(const float4*)(w + c);
        float4 bv = *(const float4*)(b + c);
        __nv_bfloat162 lo = __floats2bfloat162_rn(
            fmaf(wv.x, fast_asinh(xv.x), bv.x),
            fmaf(wv.y, fast_asinh(xv.y), bv.y));
        __nv_bfloat162 hi = __floats2bfloat162_rn(
            fmaf(wv.z, fast_asinh(xv.z), bv.z),
            fmaf(wv.w, fast_asinh(xv.w), bv.w));
        uint2 o;
        o.x = *(const uint32_t*)&lo;
        o.y = *(const uint32_t*)&hi;
        *(uint2*)(y + (size_t)idx * 4) = o;
    }
}

// ---------------------------------------------------------------------------
// Batched transpose of all 4 weights: W[K,N] -> Wt[N,K] bf16. 512 blocks.
// ---------------------------------------------------------------------------
__global__ void __launch_bounds__(256) transpose_all_kernel(
    const float* __restrict__ w0, const float* __restrict__ w1,
    const float* __restrict__ w2, const float* __restrict__ w3,
    __nv_bfloat16* __restrict__ o0, __nv_bfloat16* __restrict__ o1,
    __nv_bfloat16* __restrict__ o2, __nv_bfloat16* __restrict__ o3)
{
    __shared__ float t[32][33];
    int id = blockIdx.x;
    const float* in; __nv_bfloat16* out; int K, N, bx, by;
    if (id < 192)      { in = w0; out = o0; K = 256; N = 768; bx = id % 24;          by = id / 24; }
    else if (id < 256) { in = w1; out = o1; K = 256; N = 256; bx = (id - 192) % 8;   by = (id - 192) / 8; }
    else if (id < 384) { in = w2; out = o2; K = 256; N = 512; bx = (id - 256) % 16;  by = (id - 256) / 16; }
    else               { in = w3; out = o3; K = 512; N = 256; bx = (id - 384) % 8;   by = (id - 384) / 8; }
    int n0 = bx * 32, k0 = by * 32;
    int tx = threadIdx.x & 31, ty = threadIdx.x >> 5;  // 32 x 8
    #pragma unroll
    for (int i = 0; i < 4; i++)
        t[ty + i * 8][tx] = in[(size_t)(k0 + ty + i * 8) * N + n0 + tx];
    __syncthreads();
    #pragma unroll
    for (int i = 0; i < 4; i++)
        out[(size_t)(n0 + ty + i * 8) * K + k0 + tx] =
            __float2bfloat16_rn(t[tx][ty + i * 8]);
}

// ---------------------------------------------------------------------------
// bf16 mma.sync GEMM: C[M,N] = A[M,K] @ Bt[N,K]^T + bias (+gelu)(+res)
// Optional fused norm2: also writes h2 = bf16(n2w*asinh(C)+n2b).
// CTA 128x128, BK=64 (128B rows, XOR-swizzled), double-buffered cp.async,
// ldmatrix.x4 fragments, 8 warps x (32m x 64n).   [R9/R12 mainloop — proven]
// ---------------------------------------------------------------------------
#define BM 128
#define BN 128
#define BKE 64
#define STG (BM * BKE * 2)            // 16 KB per tile
#define GEMM_SMEM (4 * STG)           // 64 KB

template<bool GELU, bool RES, bool OUTBF16, bool NORM2>
__global__ void __launch_bounds__(256, 2)
gemm_bf16_kernel(const __nv_bfloat16* __restrict__ A,
                 const __nv_bfloat16* __restrict__ Bt,
                 const float* __restrict__ bias, const float* __restrict__ res,
                 void* __restrict__ Cout,
                 const float* __restrict__ n2w, const float* __restrict__ n2b,
                 __nv_bfloat16* __restrict__ h2out,
                 int M, int N, int K)
{
    extern __shared__ char smp[];     // [2]A + [2]B = 64 KB
    const uint32_t as_base = smem_u32(smp);
    const uint32_t bs_base = as_base + 2 * STG;

    const int tid  = threadIdx.x;
    const int wid  = tid >> 5;
    const int lane = tid & 31;
    const int g    = lane >> 2;
    const int tig  = lane & 3;
    const int wm   = wid >> 1;        // rows wm*32
    const int wn   = wid & 1;         // cols wn*64
    const int bm   = blockIdx.y * BM;
    const int bn   = blockIdx.x * BN;

    const int ar  = (lane & 7) + ((lane >> 3) & 1) * 8;
    const int acb = lane >> 4;
    const int br  = (lane & 7) + ((lane >> 4) & 1) * 8;
    const int bcb = (lane >> 3) & 1;

    float c[2][8][4];
    #pragma unroll
    for (int mt = 0; mt < 2; mt++)
        #pragma unroll
        for (int nt = 0; nt < 8; nt++)
            #pragma unroll
            for (int u = 0; u < 4; u++) c[mt][nt][u] = 0.0f;

    auto load_stage = [&](int buf, int k0) {
        const uint32_t ab = as_base + buf * STG;
        const uint32_t bb = bs_base + buf * STG;
        #pragma unroll
        for (int i = 0; i < 4; i++) {
            const int id = tid + i * 256;
            const int r = id >> 3, ch = id & 7;
            const uint32_t off = (uint32_t)(r * 128 + ((ch ^ (r & 7)) << 4));
            CP_ASYNC16(ab + off, A  + (size_t)(bm + r) * K + k0 + ch * 8);
            CP_ASYNC16(bb + off, Bt + (size_t)(bn + r) * K + k0 + ch * 8);
        }
    };

    load_stage(0, 0);
    CP_COMMIT();

    const int S = K / BKE;
    for (int s = 0; s < S; s++) {
        CP_WAIT0();
        __syncthreads();
        if (s + 1 < S) { load_stage((s + 1) & 1, (s + 1) * BKE); CP_COMMIT(); }

        const uint32_t ab = as_base + (s & 1) * STG;
        const uint32_t bb = bs_base + (s & 1) * STG;

        #pragma unroll
        for (int kk = 0; kk < 4; kk++) {
            uint32_t a[2][4], b[8][2];
            #pragma unroll
            for (int mt = 0; mt < 2; mt++) {
                const int row = wm * 32 + mt * 16 + ar;
                const uint32_t ad = ab + row * 128
                    + (((2 * kk + acb) ^ (row & 7)) << 4);
                LDSM_X4(a[mt][0], a[mt][1], a[mt][2], a[mt][3], ad);
            }
            #pragma unroll
            for (int p = 0; p < 4; p++) {
                const int row = wn * 64 + p * 16 + br;
                const uint32_t bd = bb + row * 128
                    + (((2 * kk + bcb) ^ (row & 7)) << 4);
                LDSM_X4(b[2 * p][0], b[2 * p][1], b[2 * p + 1][0], b[2 * p + 1][1], bd);
            }
            #pragma unroll
            for (int mt = 0; mt < 2; mt++)
                #pragma unroll
                for (int nt = 0; nt < 8; nt++)
                    MMA_BF16(c[mt][nt], a[mt], b[nt]);
        }
        __syncthreads();
    }

    // Epilogue: bias cached once per warp
    float bv[8][2];
    #pragma unroll
    for (int nt = 0; nt < 8; nt++) {
        const int col = bn + wn * 64 + nt * 8 + tig * 2;
        float2 bb = *(const float2*)(bias + col);
        bv[nt][0] = bb.x; bv[nt][1] = bb.y;
    }

    #pragma unroll
    for (int mt = 0; mt < 2; mt++) {
        #pragma unroll
        for (int half = 0; half < 2; half++) {
            const int row = bm + wm * 32 + mt * 16 + g + half * 8;
            #pragma unroll
            for (int nt = 0; nt < 8; nt++) {
                const int col = bn + wn * 64 + nt * 8 + tig * 2;
                float v0 = c[mt][nt][half * 2 + 0] + bv[nt][0];
                float v1 = c[mt][nt][half * 2 + 1] + bv[nt][1];
                if (GELU) { v0 = gelu_exact(v0); v1 = gelu_exact(v1); }
                if (RES) {
                    float2 r = *(const float2*)(res + (size_t)row * N + col);
                    v0 += r.x; v1 += r.y;
                }
                if (OUTBF16) {
                    *(__nv_bfloat162*)((__nv_bfloat16*)Cout + (size_t)row * N + col)
                        = __floats2bfloat162_rn(v0, v1);
                } else {
                    *(float2*)((float*)Cout + (size_t)row * N + col)
                        = make_float2(v0, v1);
                }
                if (NORM2) {
                    float h0  = fmaf(n2w[col],     fast_asinh(v0), n2b[col]);
                    float h1v = fmaf(n2w[col + 1], fast_asinh(v1), n2b[col + 1]);
                    *(__nv_bfloat162*)(h2out + (size_t)row * N + col)
                        = __floats2bfloat162_rn(h0, h1v);
                }
            }
        }
    }
}

// ---------------------------------------------------------------------------
// NATTEN 3x3: ONE warp per token, all 8 heads. Lane owns 8 contiguous
// channels; each head = one 4-lane group (2-shfl dot reduction).
// [R12 structure; (256,5) launch bounds cap regs at 51 -> 5 CTAs/SM]
// ---------------------------------------------------------------------------
__global__ void __launch_bounds__(256, 5) natten_kernel(
    const __nv_bfloat16* __restrict__ qkv, __nv_bfloat16* __restrict__ out)
{
    const int token = (blockIdx.x * 256 + threadIdx.x) >> 5;
    const int lane  = threadIdx.x & 31;
    const int c0    = lane * 8;
    const int b = token >> 12;
    const int i = (token >> 6) & 63;
    const int j = token & 63;

    const float scale = 0.17677669529663687f;  // 1/sqrt(32)

    float q[8];
    {
        uint4 qp = *(const uint4*)(qkv + (size_t)token * QKV_DIM + c0);
        const uint32_t* qu = (const uint32_t*)&qp;
        #pragma unroll
        for (int u = 0; u < 4; u++) {
            float2 f = __bfloat1622float2(*(const __nv_bfloat162*)&qu[u]);
            q[2 * u]     = f.x * scale;
            q[2 * u + 1] = f.y * scale;
        }
    }

    const int ri = min(max(i - 1, 0), 61);
    const int ci = min(max(j - 1, 0), 61);

    uint4 vv[9];
    float s[9];
    #pragma unroll
    for (int m = 0; m < 9; m++) {
        const int ni = ri + m / 3;
        const int nj = ci + m % 3;
        const __nv_bfloat16* nb = qkv + ((size_t)((b << 6) + ni) * 64 + nj) * QKV_DIM;
        uint4 kp = *(const uint4*)(nb + 256 + c0);
        vv[m]    = *(const uint4*)(nb + 512 + c0);
        const uint32_t* ku = (const uint32_t*)&kp;
        float dot = 0.0f;
        #pragma unroll
        for (int u = 0; u < 4; u++) {
            float2 f = __bfloat1622float2(*(const __nv_bfloat162*)&ku[u]);
            dot = fmaf(q[2 * u], f.x, dot);
            dot = fmaf(q[2 * u + 1], f.y, dot);
        }
        dot += __shfl_xor_sync(0xffffffffu, dot, 1);
        dot += __shfl_xor_sync(0xffffffffu, dot, 2);
        s[m] = dot;
    }

    float mx = s[0];
    #pragma unroll
    for (int m = 1; m < 9; m++) mx = fmaxf(mx, s[m]);
    float sum = 0.0f;
    #pragma unroll
    for (int m = 0; m < 9; m++) { s[m] = __expf(s[m] - mx); sum += s[m]; }
    const float inv = 1.0f / sum;

    float o[8];
    #pragma unroll
    for (int u = 0; u < 8; u++) o[u] = 0.0f;
    #pragma unroll
    for (int m = 0; m < 9; m++) {
        const uint32_t* vu = (const uint32_t*)&vv[m];
        #pragma unroll
        for (int u = 0; u < 4; u++) {
            float2 f = __bfloat1622float2(*(const __nv_bfloat162*)&vu[u]);
            o[2 * u]     = fmaf(s[m], f.x, o[2 * u]);
            o[2 * u + 1] = fmaf(s[m], f.y, o[2 * u + 1]);
        }
    }

    uint4 op;
    uint32_t* ou = (uint32_t*)&op;
    #pragma unroll
    for (int u = 0; u < 4; u++) {
        __nv_bfloat162 p = __floats2bfloat162_rn(o[2 * u] * inv, o[2 * u + 1] * inv);
        ou[u] = *(const uint32_t*)&p;
    }
    *(uint4*)(out + (size_t)token * C_DIM + c0) = op;
}

// ---------------------------------------------------------------------------
// Launcher
// ---------------------------------------------------------------------------
extern "C" void kernel_launch(void* const* d_in, const int* in_sizes, int n_in,
                              void* d_out, int out_size)
{
    (void)in_sizes; (void)n_in; (void)out_size;
    const float* h      = (const float*)d_in[0];
    const float* qkv_w  = (const float*)d_in[1];
    const float* qkv_b  = (const float*)d_in[2];
    const float* proj_w = (const float*)d_in[3];
    const float* proj_b = (const float*)d_in[4];
    const float* n1_w   = (const float*)d_in[5];
    const float* n1_b   = (const float*)d_in[6];
    const float* n2_w   = (const float*)d_in[7];
    const float* n2_b   = (const float*)d_in[8];
    const float* mlp_w1 = (const float*)d_in[9];
    const float* mlp_b1 = (const float*)d_in[10];
    const float* mlp_w2 = (const float*)d_in[11];
    const float* mlp_b2 = (const float*)d_in[12];
    float* out = (float*)d_out;

    __nv_bfloat16 *h1, *qkv, *attn, *ff, *qkvt, *projt, *mlp1t, *mlp2t;
    float *hmid;
    cudaGetSymbolAddress((void**)&h1,    g_h1);
    cudaGetSymbolAddress((void**)&qkv,   g_qkv);
    cudaGetSymbolAddress((void**)&attn,  g_attn);
    cudaGetSymbolAddress((void**)&hmid,  g_hmid);
    cudaGetSymbolAddress((void**)&ff,    g_ff);
    cudaGetSymbolAddress((void**)&qkvt,  g_qkvt);
    cudaGetSymbolAddress((void**)&projt, g_projt);
    cudaGetSymbolAddress((void**)&mlp1t, g_mlp1t);
    cudaGetSymbolAddress((void**)&mlp2t, g_mlp2t);

    cudaFuncSetAttribute(gemm_bf16_kernel<false, false, true,  false>,
                         cudaFuncAttributeMaxDynamicSharedMemorySize, GEMM_SMEM);
    cudaFuncSetAttribute(gemm_bf16_kernel<false, true,  false, true>,
                         cudaFuncAttributeMaxDynamicSharedMemorySize, GEMM_SMEM);
    cudaFuncSetAttribute(gemm_bf16_kernel<true,  false, true,  false>,
                         cudaFuncAttributeMaxDynamicSharedMemorySize, GEMM_SMEM);
    cudaFuncSetAttribute(gemm_bf16_kernel<false, true,  false, false>,
                         cudaFuncAttributeMaxDynamicSharedMemorySize, GEMM_SMEM);

    const int M = TOKENS;
    const int nElem = TOKENS * C_DIM;

    // Weight transposes (bf16), one launch
    transpose_all_kernel<<<512, 256>>>(qkv_w, proj_w, mlp_w1, mlp_w2,
                                       qkvt, projt, mlp1t, mlp2t);

    // 1. h1 = bf16(arsinh_norm(h; n1))   (x4 vectorized)
    arsinh_norm_kernel<<<(nElem / 4 + 255) / 256, 256>>>(h, n1_w, n1_b, h1, nElem / 4);

    // 2. qkv = h1 @ qkv_w + qkv_b   (bf16 out)
    gemm_bf16_kernel<false, false, true, false>
        <<<dim3(QKV_DIM / BN, M / BM), 256, GEMM_SMEM>>>(
        h1, qkvt, qkv_b, nullptr, qkv, nullptr, nullptr, nullptr,
        M, QKV_DIM, C_DIM);

    // 3. NATTEN attention (bf16 in/out), 1 warp per token
    natten_kernel<<<TOKENS / 8, 256>>>(qkv, attn);

    // 4. hmid = h + attn @ proj_w + proj_b  (fp32) ; fused h2 = norm2(hmid) bf16
    gemm_bf16_kernel<false, true, false, true>
        <<<dim3(C_DIM / BN, M / BM), 256, GEMM_SMEM>>>(
        attn, projt, proj_b, h, hmid, n2_w, n2_b, h1,
        M, C_DIM, C_DIM);

    // 5. ff = bf16(gelu(h2 @ mlp_w1 + mlp_b1))
    gemm_bf16_kernel<true, false, true, false>
        <<<dim3(FF_DIM / BN, M / BM), 256, GEMM_SMEM>>>(
        h1, mlp1t, mlp_b1, nullptr, ff, nullptr, nullptr, nullptr,
        M, FF_DIM, C_DIM);

    // 6. out = hmid + ff @ mlp_w2 + mlp_b2  (fp32)
    gemm_bf16_kernel<false, true, false, false>
        <<<dim3(C_DIM / BN, M / BM), 256, GEMM_SMEM>>>(
        ff, mlp2t, mlp_b2, hmid, out, nullptr, nullptr, nullptr,
        M, C_DIM, FF_DIM);
}

// round 16
// speedup vs baseline: 1.5931x; 1.0081x over previous
#include <cuda_runtime.h>
#include <cuda_bf16.h>
#include <cstdint>

// ---------------------------------------------------------------------------
// LocalAttentionBlock on GB300 (base sm_103 target): bf16 mma.sync m16n8k16
// GEMMs (32x64 warp tiles, double-buffered cp.async) + warp-per-token NATTEN,
// norm2 fused into proj epilogue, fast MUFU-based asinh,
// transpose+norm1 merged into one prep launch.
// B=16, H=W=64, C=256, heads=8, hd=32
// ---------------------------------------------------------------------------

#define TOKENS   65536
#define C_DIM    256
#define QKV_DIM  768
#define FF_DIM   512
#define NHEADS   8
#define HDIM     32

// Scratch (device globals — allocation-free rule)
__device__ __nv_bfloat16 g_h1  [(size_t)TOKENS * C_DIM];   // h1, then h2
__device__ __nv_bfloat16 g_qkv [(size_t)TOKENS * QKV_DIM];
__device__ __nv_bfloat16 g_attn[(size_t)TOKENS * C_DIM];
__device__ float         g_hmid[(size_t)TOKENS * C_DIM];
__device__ __nv_bfloat16 g_ff  [(size_t)TOKENS * FF_DIM];
// Transposed ([N,K] K-major, bf16) weights
__device__ __nv_bfloat16 g_qkvt [(size_t)QKV_DIM * C_DIM];
__device__ __nv_bfloat16 g_projt[(size_t)C_DIM * C_DIM];
__device__ __nv_bfloat16 g_mlp1t[(size_t)FF_DIM * C_DIM];
__device__ __nv_bfloat16 g_mlp2t[(size_t)C_DIM * FF_DIM];

// ---------------------------------------------------------------------------
// Helpers
// ---------------------------------------------------------------------------
__device__ __forceinline__ uint32_t smem_u32(const void* p) {
    uint32_t a;
    asm("{ .reg .u64 t; cvta.to.shared.u64 t, %1; cvt.u32.u64 %0, t; }"
        : "=r"(a) : "l"(p));
    return a;
}
#define CP_ASYNC16(dst, src) \
    asm volatile("cp.async.cg.shared.global [%0], [%1], 16;" :: "r"(dst), "l"(src))
#define CP_COMMIT() asm volatile("cp.async.commit_group;" ::: "memory")
#define CP_WAIT0()  asm volatile("cp.async.wait_group 0;" ::: "memory")

#define LDSM_X4(r0, r1, r2, r3, addr) \
    asm volatile("ldmatrix.sync.aligned.m8n8.x4.shared.b16 {%0,%1,%2,%3}, [%4];" \
        : "=r"(r0), "=r"(r1), "=r"(r2), "=r"(r3) : "r"(addr))

#define MMA_BF16(cf, av, bv) \
    asm volatile("mma.sync.aligned.m16n8k16.row.col.f32.bf16.bf16.f32 " \
        "{%0,%1,%2,%3}, {%4,%5,%6,%7}, {%8,%9}, {%0,%1,%2,%3};" \
        : "+f"((cf)[0]), "+f"((cf)[1]), "+f"((cf)[2]), "+f"((cf)[3]) \
        : "r"((av)[0]), "r"((av)[1]), "r"((av)[2]), "r"((av)[3]), \
          "r"((bv)[0]), "r"((bv)[1]))

__device__ __forceinline__ float gelu_exact(float v) {
    return 0.5f * v * (1.0f + erff(v * 0.70710678118654752440f));
}

// Fast asinh: |x| form avoids cancellation; inputs are O(1..100) so no
// overflow path needed. __logf/sqrt.approx rel err ~5e-7 << bf16 floor.
__device__ __forceinline__ float fast_asinh(float x) {
    float s = fabsf(x);
    float t = fmaf(s, s, 1.0f);
    float q;
    asm("sqrt.approx.f32 %0, %1;" : "=f"(q) : "f"(t));
    float r = __logf(s + q);
    return copysignf(r, x);
}

// ---------------------------------------------------------------------------
// Prep kernel: one launch doing BOTH independent prologue jobs.
//   blocks [0, 512):   transpose 4 weights W[K,N] -> Wt[N,K] bf16
//   blocks [512, ...): h1 = bf16(n1w*asinh(h)+n1b), x4 vectorized
// ---------------------------------------------------------------------------
#define PREP_TRANS_BLOCKS 512
#define PREP_NORM_BLOCKS  (TOKENS * C_DIM / 4 / 256)   // 16384
#define PREP_BLOCKS       (PREP_TRANS_BLOCKS + PREP_NORM_BLOCKS)

__global__ void __launch_bounds__(256) prep_kernel(
    const float* __restrict__ w0, const float* __restrict__ w1,
    const float* __restrict__ w2, const float* __restrict__ w3,
    __nv_bfloat16* __restrict__ o0, __nv_bfloat16* __restrict__ o1,
    __nv_bfloat16* __restrict__ o2, __nv_bfloat16* __restrict__ o3,
    const float* __restrict__ x, const float* __restrict__ nw,
    const float* __restrict__ nb, __nv_bfloat16* __restrict__ y)
{
    const int id = blockIdx.x;
    if (id >= PREP_TRANS_BLOCKS) {
        // ---- norm part ----
        int idx = (id - PREP_TRANS_BLOCKS) * 256 + threadIdx.x;
        int c = (idx * 4) & (C_DIM - 1);
        float4 xv = *(const float4*)(x + (size_t)idx * 4);
        float4 wv = *(const float4*)(nw + c);
        float4 bv = *(const float4*)(nb + c);
        __nv_bfloat162 lo = __floats2bfloat162_rn(
            fmaf(wv.x, fast_asinh(xv.x), bv.x),
            fmaf(wv.y, fast_asinh(xv.y), bv.y));
        __nv_bfloat162 hi = __floats2bfloat162_rn(
            fmaf(wv.z, fast_asinh(xv.z), bv.z),
            fmaf(wv.w, fast_asinh(xv.w), bv.w));
        uint2 o;
        o.x = *(const uint32_t*)&lo;
        o.y = *(const uint32_t*)&hi;
        *(uint2*)(y + (size_t)idx * 4) = o;
        return;
    }
    // ---- transpose part ----
    __shared__ float t[32][33];
    const float* in; __nv_bfloat16* out; int K, N, bx, by;
    if (id < 192)      { in = w0; out = o0; K = 256; N = 768; bx = id % 24;          by = id / 24; }
    else if (id < 256) { in = w1; out = o1; K = 256; N = 256; bx = (id - 192) % 8;   by = (id - 192) / 8; }
    else if (id < 384) { in = w2; out = o2; K = 256; N = 512; bx = (id - 256) % 16;  by = (id - 256) / 16; }
    else               { in = w3; out = o3; K = 512; N = 256; bx = (id - 384) % 8;   by = (id - 384) / 8; }
    int n0 = bx * 32, k0 = by * 32;
    int tx = threadIdx.x & 31, ty = threadIdx.x >> 5;  // 32 x 8
    #pragma unroll
    for (int i = 0; i < 4; i++)
        t[ty + i * 8][tx] = in[(size_t)(k0 + ty + i * 8) * N + n0 + tx];
    __syncthreads();
    #pragma unroll
    for (int i = 0; i < 4; i++)
        out[(size_t)(n0 + ty + i * 8) * K + k0 + tx] =
            __float2bfloat16_rn(t[tx][ty + i * 8]);
}

// ---------------------------------------------------------------------------
// bf16 mma.sync GEMM: C[M,N] = A[M,K] @ Bt[N,K]^T + bias (+gelu)(+res)
// Optional fused norm2: also writes h2 = bf16(n2w*asinh(C)+n2b).
// CTA 128x128, BK=64 (128B rows, XOR-swizzled), double-buffered cp.async,
// ldmatrix.x4 fragments, 8 warps x (32m x 64n).   [R9/R12 mainloop — proven]
// ---------------------------------------------------------------------------
#define BM 128
#define BN 128
#define BKE 64
#define STG (BM * BKE * 2)            // 16 KB per tile
#define GEMM_SMEM (4 * STG)           // 64 KB

template<bool GELU, bool RES, bool OUTBF16, bool NORM2>
__global__ void __launch_bounds__(256, 2)
gemm_bf16_kernel(const __nv_bfloat16* __restrict__ A,
                 const __nv_bfloat16* __restrict__ Bt,
                 const float* __restrict__ bias, const float* __restrict__ res,
                 void* __restrict__ Cout,
                 const float* __restrict__ n2w, const float* __restrict__ n2b,
                 __nv_bfloat16* __restrict__ h2out,
                 int M, int N, int K)
{
    extern __shared__ char smp[];     // [2]A + [2]B = 64 KB
    const uint32_t as_base = smem_u32(smp);
    const uint32_t bs_base = as_base + 2 * STG;

    const int tid  = threadIdx.x;
    const int wid  = tid >> 5;
    const int lane = tid & 31;
    const int g    = lane >> 2;
    const int tig  = lane & 3;
    const int wm   = wid >> 1;        // rows wm*32
    const int wn   = wid & 1;         // cols wn*64
    const int bm   = blockIdx.y * BM;
    const int bn   = blockIdx.x * BN;

    const int ar  = (lane & 7) + ((lane >> 3) & 1) * 8;
    const int acb = lane >> 4;
    const int br  = (lane & 7) + ((lane >> 4) & 1) * 8;
    const int bcb = (lane >> 3) & 1;

    float c[2][8][4];
    #pragma unroll
    for (int mt = 0; mt < 2; mt++)
        #pragma unroll
        for (int nt = 0; nt < 8; nt++)
            #pragma unroll
            for (int u = 0; u < 4; u++) c[mt][nt][u] = 0.0f;

    auto load_stage = [&](int buf, int k0) {
        const uint32_t ab = as_base + buf * STG;
        const uint32_t bb = bs_base + buf * STG;
        #pragma unroll
        for (int i = 0; i < 4; i++) {
            const int id = tid + i * 256;
            const int r = id >> 3, ch = id & 7;
            const uint32_t off = (uint32_t)(r * 128 + ((ch ^ (r & 7)) << 4));
            CP_ASYNC16(ab + off, A  + (size_t)(bm + r) * K + k0 + ch * 8);
            CP_ASYNC16(bb + off, Bt + (size_t)(bn + r) * K + k0 + ch * 8);
        }
    };

    load_stage(0, 0);
    CP_COMMIT();

    const int S = K / BKE;
    for (int s = 0; s < S; s++) {
        CP_WAIT0();
        __syncthreads();
        if (s + 1 < S) { load_stage((s + 1) & 1, (s + 1) * BKE); CP_COMMIT(); }

        const uint32_t ab = as_base + (s & 1) * STG;
        const uint32_t bb = bs_base + (s & 1) * STG;

        #pragma unroll
        for (int kk = 0; kk < 4; kk++) {
            uint32_t a[2][4], b[8][2];
            #pragma unroll
            for (int mt = 0; mt < 2; mt++) {
                const int row = wm * 32 + mt * 16 + ar;
                const uint32_t ad = ab + row * 128
                    + (((2 * kk + acb) ^ (row & 7)) << 4);
                LDSM_X4(a[mt][0], a[mt][1], a[mt][2], a[mt][3], ad);
            }
            #pragma unroll
            for (int p = 0; p < 4; p++) {
                const int row = wn * 64 + p * 16 + br;
                const uint32_t bd = bb + row * 128
                    + (((2 * kk + bcb) ^ (row & 7)) << 4);
                LDSM_X4(b[2 * p][0], b[2 * p][1], b[2 * p + 1][0], b[2 * p + 1][1], bd);
            }
            #pragma unroll
            for (int mt = 0; mt < 2; mt++)
                #pragma unroll
                for (int nt = 0; nt < 8; nt++)
                    MMA_BF16(c[mt][nt], a[mt], b[nt]);
        }
        __syncthreads();
    }

    // Epilogue: bias cached once per warp
    float bv[8][2];
    #pragma unroll
    for (int nt = 0; nt < 8; nt++) {
        const int col = bn + wn * 64 + nt * 8 + tig * 2;
        float2 bb = *(const float2*)(bias + col);
        bv[nt][0] = bb.x; bv[nt][1] = bb.y;
    }

    #pragma unroll
    for (int mt = 0; mt < 2; mt++) {
        #pragma unroll
        for (int half = 0; half < 2; half++) {
            const int row = bm + wm * 32 + mt * 16 + g + half * 8;
            #pragma unroll
            for (int nt = 0; nt < 8; nt++) {
                const int col = bn + wn * 64 + nt * 8 + tig * 2;
                float v0 = c[mt][nt][half * 2 + 0] + bv[nt][0];
                float v1 = c[mt][nt][half * 2 + 1] + bv[nt][1];
                if (GELU) { v0 = gelu_exact(v0); v1 = gelu_exact(v1); }
                if (RES) {
                    float2 r = *(const float2*)(res + (size_t)row * N + col);
                    v0 += r.x; v1 += r.y;
                }
                if (OUTBF16) {
                    *(__nv_bfloat162*)((__nv_bfloat16*)Cout + (size_t)row * N + col)
                        = __floats2bfloat162_rn(v0, v1);
                } else {
                    *(float2*)((float*)Cout + (size_t)row * N + col)
                        = make_float2(v0, v1);
                }
                if (NORM2) {
                    float h0  = fmaf(n2w[col],     fast_asinh(v0), n2b[col]);
                    float h1v = fmaf(n2w[col + 1], fast_asinh(v1), n2b[col + 1]);
                    *(__nv_bfloat162*)(h2out + (size_t)row * N + col)
                        = __floats2bfloat162_rn(h0, h1v);
                }
            }
        }
    }
}

// ---------------------------------------------------------------------------
// NATTEN 3x3: ONE warp per token, all 8 heads. Lane owns 8 contiguous
// channels; each head = one 4-lane group (2-shfl dot reduction).
// [exact R12 structure — best measured]
// ---------------------------------------------------------------------------
__global__ void __launch_bounds__(256) natten_kernel(
    const __nv_bfloat16* __restrict__ qkv, __nv_bfloat16* __restrict__ out)
{
    const int token = (blockIdx.x * 256 + threadIdx.x) >> 5;
    const int lane  = threadIdx.x & 31;
    const int c0    = lane * 8;
    const int b = token >> 12;
    const int i = (token >> 6) & 63;
    const int j = token & 63;

    const float scale = 0.17677669529663687f;  // 1/sqrt(32)

    float q[8];
    {
        uint4 qp = *(const uint4*)(qkv + (size_t)token * QKV_DIM + c0);
        const uint32_t* qu = (const uint32_t*)&qp;
        #pragma unroll
        for (int u = 0; u < 4; u++) {
            float2 f = __bfloat1622float2(*(const __nv_bfloat162*)&qu[u]);
            q[2 * u]     = f.x * scale;
            q[2 * u + 1] = f.y * scale;
        }
    }

    const int ri = min(max(i - 1, 0), 61);
    const int ci = min(max(j - 1, 0), 61);

    uint4 vv[9];
    float s[9];
    #pragma unroll
    for (int m = 0; m < 9; m++) {
        const int ni = ri + m / 3;
        const int nj = ci + m % 3;
        const __nv_bfloat16* nb = qkv + ((size_t)((b << 6) + ni) * 64 + nj) * QKV_DIM;
        uint4 kp = *(const uint4*)(nb + 256 + c0);
        vv[m]    = *(const uint4*)(nb + 512 + c0);
        const uint32_t* ku = (const uint32_t*)&kp;
        float dot = 0.0f;
        #pragma unroll
        for (int u = 0; u < 4; u++) {
            float2 f = __bfloat1622float2(*(const __nv_bfloat162*)&ku[u]);
            dot = fmaf(q[2 * u], f.x, dot);
            dot = fmaf(q[2 * u + 1], f.y, dot);
        }
        dot += __shfl_xor_sync(0xffffffffu, dot, 1);
        dot += __shfl_xor_sync(0xffffffffu, dot, 2);
        s[m] = dot;
    }

    float mx = s[0];
    #pragma unroll
    for (int m = 1; m < 9; m++) mx = fmaxf(mx, s[m]);
    float sum = 0.0f;
    #pragma unroll
    for (int m = 0; m < 9; m++) { s[m] = __expf(s[m] - mx); sum += s[m]; }
    const float inv = 1.0f / sum;

    float o[8];
    #pragma unroll
    for (int u = 0; u < 8; u++) o[u] = 0.0f;
    #pragma unroll
    for (int m = 0; m < 9; m++) {
        const uint32_t* vu = (const uint32_t*)&vv[m];
        #pragma unroll
        for (int u = 0; u < 4; u++) {
            float2 f = __bfloat1622float2(*(const __nv_bfloat162*)&vu[u]);
            o[2 * u]     = fmaf(s[m], f.x, o[2 * u]);
            o[2 * u + 1] = fmaf(s[m], f.y, o[2 * u + 1]);
        }
    }

    uint4 op;
    uint32_t* ou = (uint32_t*)&op;
    #pragma unroll
    for (int u = 0; u < 4; u++) {
        __nv_bfloat162 p = __floats2bfloat162_rn(o[2 * u] * inv, o[2 * u + 1] * inv);
        ou[u] = *(const uint32_t*)&p;
    }
    *(uint4*)(out + (size_t)token * C_DIM + c0) = op;
}

// ---------------------------------------------------------------------------
// Launcher
// ---------------------------------------------------------------------------
extern "C" void kernel_launch(void* const* d_in, const int* in_sizes, int n_in,
                              void* d_out, int out_size)
{
    (void)in_sizes; (void)n_in; (void)out_size;
    const float* h      = (const float*)d_in[0];
    const float* qkv_w  = (const float*)d_in[1];
    const float* qkv_b  = (const float*)d_in[2];
    const float* proj_w = (const float*)d_in[3];
    const float* proj_b = (const float*)d_in[4];
    const float* n1_w   = (const float*)d_in[5];
    const float* n1_b   = (const float*)d_in[6];
    const float* n2_w   = (const float*)d_in[7];
    const float* n2_b   = (const float*)d_in[8];
    const float* mlp_w1 = (const float*)d_in[9];
    const float* mlp_b1 = (const float*)d_in[10];
    const float* mlp_w2 = (const float*)d_in[11];
    const float* mlp_b2 = (const float*)d_in[12];
    float* out = (float*)d_out;

    __nv_bfloat16 *h1, *qkv, *attn, *ff, *qkvt, *projt, *mlp1t, *mlp2t;
    float *hmid;
    cudaGetSymbolAddress((void**)&h1,    g_h1);
    cudaGetSymbolAddress((void**)&qkv,   g_qkv);
    cudaGetSymbolAddress((void**)&attn,  g_attn);
    cudaGetSymbolAddress((void**)&hmid,  g_hmid);
    cudaGetSymbolAddress((void**)&ff,    g_ff);
    cudaGetSymbolAddress((void**)&qkvt,  g_qkvt);
    cudaGetSymbolAddress((void**)&projt, g_projt);
    cudaGetSymbolAddress((void**)&mlp1t, g_mlp1t);
    cudaGetSymbolAddress((void**)&mlp2t, g_mlp2t);

    cudaFuncSetAttribute(gemm_bf16_kernel<false, false, true,  false>,
                         cudaFuncAttributeMaxDynamicSharedMemorySize, GEMM_SMEM);
    cudaFuncSetAttribute(gemm_bf16_kernel<false, true,  false, true>,
                         cudaFuncAttributeMaxDynamicSharedMemorySize, GEMM_SMEM);
    cudaFuncSetAttribute(gemm_bf16_kernel<true,  false, true,  false>,
                         cudaFuncAttributeMaxDynamicSharedMemorySize, GEMM_SMEM);
    cudaFuncSetAttribute(gemm_bf16_kernel<false, true,  false, false>,
                         cudaFuncAttributeMaxDynamicSharedMemorySize, GEMM_SMEM);

    const int M = TOKENS;

    // 0. Prologue: weight transposes + h1 = bf16(arsinh_norm(h; n1)), ONE launch
    prep_kernel<<<PREP_BLOCKS, 256>>>(qkv_w, proj_w, mlp_w1, mlp_w2,
                                      qkvt, projt, mlp1t, mlp2t,
                                      h, n1_w, n1_b, h1);

    // 1. qkv = h1 @ qkv_w + qkv_b   (bf16 out)
    gemm_bf16_kernel<false, false, true, false>
        <<<dim3(QKV_DIM / BN, M / BM), 256, GEMM_SMEM>>>(
        h1, qkvt, qkv_b, nullptr, qkv, nullptr, nullptr, nullptr,
        M, QKV_DIM, C_DIM);

    // 2. NATTEN attention (bf16 in/out), 1 warp per token
    natten_kernel<<<TOKENS / 8, 256>>>(qkv, attn);

    // 3. hmid = h + attn @ proj_w + proj_b  (fp32) ; fused h2 = norm2(hmid) bf16
    gemm_bf16_kernel<false, true, false, true>
        <<<dim3(C_DIM / BN, M / BM), 256, GEMM_SMEM>>>(
        attn, projt, proj_b, h, hmid, n2_w, n2_b, h1,
        M, C_DIM, C_DIM);

    // 4. ff = bf16(gelu(h2 @ mlp_w1 + mlp_b1))
    gemm_bf16_kernel<true, false, true, false>
        <<<dim3(FF_DIM / BN, M / BM), 256, GEMM_SMEM>>>(
        h1, mlp1t, mlp_b1, nullptr, ff, nullptr, nullptr, nullptr,
        M, FF_DIM, C_DIM);

    // 5. out = hmid + ff @ mlp_w2 + mlp_b2  (fp32)
    gemm_bf16_kernel<false, true, false, false>
        <<<dim3(C_DIM / BN, M / BM), 256, GEMM_SMEM>>>(
        ff, mlp2t, mlp_b2, hmid, out, nullptr, nullptr, nullptr,
        M, C_DIM, FF_DIM);
}